// round 12
// baseline (speedup 1.0000x reference)
#include <cuda_runtime.h>
#include <cuda_bf16.h>

// TelephotoInterp R12: R11 (best 75.8us) with ONE change — __launch_bounds__(256,7)
// (36-reg target -> 7 blocks/SM = 56 warps, 87.5% theoretical occupancy, vs 42
// regs -> 6 blocks -> 75%). Tests the overlap-gap theory at half the register
// squeeze that made R7 spill.

__device__ __forceinline__ float fsqrt_ap(float x) {
    float r; asm("sqrt.approx.f32 %0, %1;" : "=f"(r) : "f"(x)); return r;
}
__device__ __forceinline__ float frcp_ap(float x) {
    float r; asm("rcp.approx.f32 %0, %1;" : "=f"(r) : "f"(x)); return r;
}
__device__ __forceinline__ float frsqrt_ap(float x) {
    float r; asm("rsqrt.approx.f32 %0, %1;" : "=f"(r) : "f"(x)); return r;
}
__device__ __forceinline__ void red_add_v4(float* addr, float a, float b, float c, float d) {
    asm volatile("red.global.add.v4.f32 [%0], {%1, %2, %3, %4};"
                 :: "l"(addr), "f"(a), "f"(b), "f"(c), "f"(d) : "memory");
}

// Wrap g into [0, fres): covers g in (-2*fres, 2*fres); the trailing subtracts
// also absorb the rounding case where a tiny-negative g + fres rounds to fres.
__device__ __forceinline__ float wrapf(float g, float fres) {
    g = (g <  0.0f) ? g + fres : g;
    g = (g <  0.0f) ? g + fres : g;
    g = (g >= fres) ? g - fres : g;
    g = (g >= fres) ? g - fres : g;
    return g;
}

__global__ void __launch_bounds__(256, 7) telephoto_paint_kernel(
    const float4* __restrict__ pos4,
    const float4* __restrict__ vel4,
    const float* __restrict__ rotations,
    const float* __restrict__ observer,
    const float* __restrict__ r_centers,
    const float* __restrict__ widths,
    const float* __restrict__ t_p,
    const float* __restrict__ maxd_p,
    const float* __restrict__ box_p,
    const int*   __restrict__ shell_p,
    const int*   __restrict__ rotidx_p,
    const int*   __restrict__ res_p,
    float* __restrict__ out,
    int n)   // n = number of particles
{
    const int t = blockIdx.x * blockDim.x + threadIdx.x;
    const int base = 4 * t;
    if (base >= n) return;

    // Scalar params (uniform broadcast loads)
    const int   shell = shell_p[0];
    const float rc    = r_centers[shell];
    const float w     = widths[shell];
    const float maxd  = maxd_p[0];
    const float box   = box_p[0];
    const int   res   = res_p[0];
    const float fres  = (float)res;
    const bool inside = (rc + 0.5f * w <= maxd);
    const bool v4ok   = ((res & 3) == 0);
    const float ox = observer[0], oy = observer[1], oz = observer[2];
    const float zlo = rc - 0.5f * w;
    const float zhi = rc + 0.5f * w;
    const float scale = (float)res / box;

    // Rotation / drift params (only meaningful for telephoto branch)
    float m00=1.f,m01=0.f,m02=0.f,m10=0.f,m11=1.f,m12=0.f,m20=0.f,m21=0.f,m22=1.f;
    float tt = 0.f, shift = 0.f, gp_t = 0.f;
    if (!inside) {
        const int ridx = rotidx_p[0] % 47;
        const float* __restrict__ M = rotations + 9 * ridx;
        m00=M[0]; m01=M[1]; m02=M[2];
        m10=M[3]; m11=M[4]; m12=M[5];
        m20=M[6]; m21=M[7]; m22=M[8];
        tt = t_p[0];
        shift = floorf(rc / maxd) * maxd;
        gp_t = tt * sqrtf(tt);   // uniform scalar, IEEE is fine
    }

    // Vectorized loads: 4 particles = 12 floats = 3 float4 per array.
    const float4 pA = pos4[3*t + 0];
    const float4 pB = pos4[3*t + 1];
    const float4 pC = pos4[3*t + 2];
    const float4 vA = vel4[3*t + 0];
    const float4 vB = vel4[3*t + 1];
    const float4 vC = vel4[3*t + 2];

    float px[4] = {pA.x, pA.w, pB.z, pC.y};
    float py[4] = {pA.y, pB.x, pB.w, pC.z};
    float pz[4] = {pA.z, pB.y, pC.x, pC.w};
    float vx[4] = {vA.x, vA.w, vB.z, vC.y};
    float vy[4] = {vA.y, vB.x, vB.w, vC.z};
    float vz[4] = {vA.z, vB.y, vC.x, vC.w};

    #pragma unroll
    for (int k = 0; k < 4; k++) {
        if (base + k >= n) break;

        float X, Y;
        if (inside) {
            const float Z = pz[k];
            if (!(Z >= zlo && Z < zhi)) continue;   // sel==0 adds +0.0 -> skip
            X = px[k]; Y = py[k];
        } else {
            const float qx = px[k] - ox, qy = py[k] - oy, qz = pz[k] - oz;
            const float rx = m00*qx + m01*qy + m02*qz;
            const float ry = m10*qx + m11*qy + m12*qz;
            const float rz = m20*qx + m21*qy + m22*qz + shift;

            const float dxd = rx - ox, dyd = ry - oy, dzd = rz - oz;
            const float d2   = fmaf(dxd, dxd, fmaf(dyd, dyd, dzd*dzd));
            const float dist = fsqrt_ap(d2);

            const float a_tgt = frcp_ap(fmaf(dist, (1.0f/3000.0f), 1.0f));
            const float gp_a  = a_tgt * fsqrt_ap(a_tgt);          // a^1.5
            const float inv_q = frsqrt_ap(fsqrt_ap(tt * a_tgt));  // (t*a)^-0.25
            const float drift = (gp_a - gp_t) * (2.0f/3.0f) * inv_q;

            const float wz = m20*vx[k] + m21*vy[k] + m22*vz[k];
            const float Z  = rz + drift * wz + oz;
            if (!(Z >= zlo && Z < zhi)) continue;   // sel==0 adds +0.0 -> skip

            // Only accepted particles pay for X/Y
            const float wx = m00*vx[k] + m01*vy[k] + m02*vz[k];
            const float wy = m10*vx[k] + m11*vy[k] + m12*vz[k];
            X = rx + drift * wx + ox;
            Y = ry + drift * wy + oy;
        }

        // Float-domain periodic wrap, then floor (no integer modulo needed)
        const float xg = wrapf(X * scale, fres);
        const float yg = wrapf(Y * scale, fres);

        const int ix0 = (int)xg;        // xg in [0, fres) -> trunc == floor
        const int iy0 = (int)yg;
        const float fx = xg - (float)ix0;
        const float fy = yg - (float)iy0;
        int ix1 = ix0 + 1; if (ix1 == res) ix1 = 0;

        const float w00 = (1.0f - fx) * (1.0f - fy);
        const float w10 = fx * (1.0f - fy);
        const float w01 = (1.0f - fx) * fy;
        const float w11 = fx * fy;

        if (v4ok) {
            // Branch-free uniform scatter: per row, one v4 at the 16B window
            // containing iy0 (weights placed via selects; for o==3 the high
            // weight falls outside -> zeros), plus one predicated v4 at the
            // next window's lane 0 for the o==3 spill-over (handles y-wrap).
            const int o   = iy0 & 3;
            const int iyb = iy0 & ~3;

            const bool e0 = (o == 0), e1 = (o == 1), e2 = (o == 2), e3 = (o == 3);

            const float a0 = e0 ? w00 : 0.0f;
            const float a1 = e1 ? w00 : (e0 ? w01 : 0.0f);
            const float a2 = e2 ? w00 : (e1 ? w01 : 0.0f);
            const float a3 = e3 ? w00 : (e2 ? w01 : 0.0f);

            const float b0 = e0 ? w10 : 0.0f;
            const float b1 = e1 ? w10 : (e0 ? w11 : 0.0f);
            const float b2 = e2 ? w10 : (e1 ? w11 : 0.0f);
            const float b3 = e3 ? w10 : (e2 ? w11 : 0.0f);

            red_add_v4(&out[ix0 * res + iyb], a0, a1, a2, a3);
            red_add_v4(&out[ix1 * res + iyb], b0, b1, b2, b3);

            if (e3) {
                int iy1 = iy0 + 1; if (iy1 == res) iy1 = 0;   // iy1 % 4 == 0
                red_add_v4(&out[ix0 * res + iy1], w01, 0.0f, 0.0f, 0.0f);
                red_add_v4(&out[ix1 * res + iy1], w11, 0.0f, 0.0f, 0.0f);
            }
        } else {
            int iy1 = iy0 + 1; if (iy1 == res) iy1 = 0;
            atomicAdd(&out[ix0 * res + iy0], w00);
            atomicAdd(&out[ix1 * res + iy0], w10);
            atomicAdd(&out[ix0 * res + iy1], w01);
            atomicAdd(&out[ix1 * res + iy1], w11);
        }
    }
}

extern "C" void kernel_launch(void* const* d_in, const int* in_sizes, int n_in,
                              void* d_out, int out_size) {
    const float* positions  = (const float*)d_in[0];
    const float* velocities = (const float*)d_in[1];
    const float* rotations  = (const float*)d_in[2];
    const float* observer   = (const float*)d_in[3];
    const float* r_centers  = (const float*)d_in[4];
    const float* widths     = (const float*)d_in[5];
    const float* t_p        = (const float*)d_in[6];
    const float* maxd_p     = (const float*)d_in[7];
    const float* box_p      = (const float*)d_in[8];
    const int*   shell_p    = (const int*)d_in[9];
    const int*   rotidx_p   = (const int*)d_in[10];
    const int*   res_p      = (const int*)d_in[11];
    float* out = (float*)d_out;

    const int n = in_sizes[0] / 3;

    cudaMemsetAsync(out, 0, (size_t)out_size * sizeof(float));

    const int threads = 256;
    const int nthreads_needed = (n + 3) / 4;
    const int blocks = (nthreads_needed + threads - 1) / threads;
    telephoto_paint_kernel<<<blocks, threads>>>(
        (const float4*)positions, (const float4*)velocities,
        rotations, observer, r_centers, widths,
        t_p, maxd_p, box_p, shell_p, rotidx_p, res_p, out, n);
}

// round 13
// speedup vs baseline: 1.1789x; 1.1789x over previous
#include <cuda_runtime.h>
#include <cuda_bf16.h>

// TelephotoInterp R13: R11 scatter/math unchanged; ONE structural change —
// 2 particles/thread with float2 (LDG.64) loads, halving staged register state
// (24 -> 12 floats) to raise natural spill-free occupancy (target ~36 regs).

__device__ __forceinline__ float fsqrt_ap(float x) {
    float r; asm("sqrt.approx.f32 %0, %1;" : "=f"(r) : "f"(x)); return r;
}
__device__ __forceinline__ float frcp_ap(float x) {
    float r; asm("rcp.approx.f32 %0, %1;" : "=f"(r) : "f"(x)); return r;
}
__device__ __forceinline__ float frsqrt_ap(float x) {
    float r; asm("rsqrt.approx.f32 %0, %1;" : "=f"(r) : "f"(x)); return r;
}
__device__ __forceinline__ void red_add_v4(float* addr, float a, float b, float c, float d) {
    asm volatile("red.global.add.v4.f32 [%0], {%1, %2, %3, %4};"
                 :: "l"(addr), "f"(a), "f"(b), "f"(c), "f"(d) : "memory");
}

__device__ __forceinline__ float wrapf(float g, float fres) {
    g = (g <  0.0f) ? g + fres : g;
    g = (g <  0.0f) ? g + fres : g;
    g = (g >= fres) ? g - fres : g;
    g = (g >= fres) ? g - fres : g;
    return g;
}

__global__ void telephoto_paint_kernel(
    const float2* __restrict__ pos2,
    const float2* __restrict__ vel2,
    const float* __restrict__ rotations,
    const float* __restrict__ observer,
    const float* __restrict__ r_centers,
    const float* __restrict__ widths,
    const float* __restrict__ t_p,
    const float* __restrict__ maxd_p,
    const float* __restrict__ box_p,
    const int*   __restrict__ shell_p,
    const int*   __restrict__ rotidx_p,
    const int*   __restrict__ res_p,
    float* __restrict__ out,
    int n)   // n = number of particles
{
    const int t = blockIdx.x * blockDim.x + threadIdx.x;
    const int base = 2 * t;
    if (base >= n) return;

    // Scalar params (uniform broadcast loads)
    const int   shell = shell_p[0];
    const float rc    = r_centers[shell];
    const float w     = widths[shell];
    const float maxd  = maxd_p[0];
    const float box   = box_p[0];
    const int   res   = res_p[0];
    const float fres  = (float)res;
    const bool inside = (rc + 0.5f * w <= maxd);
    const bool v4ok   = ((res & 3) == 0);
    const float ox = observer[0], oy = observer[1], oz = observer[2];
    const float zlo = rc - 0.5f * w;
    const float zhi = rc + 0.5f * w;
    const float scale = (float)res / box;

    // Rotation / drift params (only meaningful for telephoto branch)
    float m00=1.f,m01=0.f,m02=0.f,m10=0.f,m11=1.f,m12=0.f,m20=0.f,m21=0.f,m22=1.f;
    float tt = 0.f, shift = 0.f, gp_t = 0.f;
    if (!inside) {
        const int ridx = rotidx_p[0] % 47;
        const float* __restrict__ M = rotations + 9 * ridx;
        m00=M[0]; m01=M[1]; m02=M[2];
        m10=M[3]; m11=M[4]; m12=M[5];
        m20=M[6]; m21=M[7]; m22=M[8];
        tt = t_p[0];
        shift = floorf(rc / maxd) * maxd;
        gp_t = tt * sqrtf(tt);   // uniform scalar, IEEE is fine
    }

    // 2 particles = 6 floats = 3 float2 per array (always 8B-aligned).
    float px[2], py[2], pz[2], vx[2], vy[2], vz[2];
    int cnt = 2;
    if (base + 1 < n) {
        const float2 pA = pos2[3*t + 0];   // x0 y0
        const float2 pB = pos2[3*t + 1];   // z0 x1
        const float2 pC = pos2[3*t + 2];   // y1 z1
        px[0]=pA.x; py[0]=pA.y; pz[0]=pB.x;
        px[1]=pB.y; py[1]=pC.x; pz[1]=pC.y;
        if (!inside) {
            const float2 vA = vel2[3*t + 0];
            const float2 vB = vel2[3*t + 1];
            const float2 vC = vel2[3*t + 2];
            vx[0]=vA.x; vy[0]=vA.y; vz[0]=vB.x;
            vx[1]=vB.y; vy[1]=vC.x; vz[1]=vC.y;
        }
    } else {
        cnt = 1;
        const float* pp = (const float*)pos2;
        const float* vv = (const float*)vel2;
        px[0] = pp[3*base+0]; py[0] = pp[3*base+1]; pz[0] = pp[3*base+2];
        if (!inside) {
            vx[0] = vv[3*base+0]; vy[0] = vv[3*base+1]; vz[0] = vv[3*base+2];
        }
    }

    #pragma unroll
    for (int k = 0; k < 2; k++) {
        if (k >= cnt) break;

        float X, Y;
        if (inside) {
            const float Z = pz[k];
            if (!(Z >= zlo && Z < zhi)) continue;   // sel==0 adds +0.0 -> skip
            X = px[k]; Y = py[k];
        } else {
            const float qx = px[k] - ox, qy = py[k] - oy, qz = pz[k] - oz;
            const float rx = m00*qx + m01*qy + m02*qz;
            const float ry = m10*qx + m11*qy + m12*qz;
            const float rz = m20*qx + m21*qy + m22*qz + shift;

            const float dxd = rx - ox, dyd = ry - oy, dzd = rz - oz;
            const float d2   = fmaf(dxd, dxd, fmaf(dyd, dyd, dzd*dzd));
            const float dist = fsqrt_ap(d2);

            const float a_tgt = frcp_ap(fmaf(dist, (1.0f/3000.0f), 1.0f));
            const float gp_a  = a_tgt * fsqrt_ap(a_tgt);          // a^1.5
            const float inv_q = frsqrt_ap(fsqrt_ap(tt * a_tgt));  // (t*a)^-0.25
            const float drift = (gp_a - gp_t) * (2.0f/3.0f) * inv_q;

            const float wz = m20*vx[k] + m21*vy[k] + m22*vz[k];
            const float Z  = rz + drift * wz + oz;
            if (!(Z >= zlo && Z < zhi)) continue;   // sel==0 adds +0.0 -> skip

            // Only accepted particles pay for X/Y
            const float wx = m00*vx[k] + m01*vy[k] + m02*vz[k];
            const float wy = m10*vx[k] + m11*vy[k] + m12*vz[k];
            X = rx + drift * wx + ox;
            Y = ry + drift * wy + oy;
        }

        // Float-domain periodic wrap, then floor (no integer modulo needed)
        const float xg = wrapf(X * scale, fres);
        const float yg = wrapf(Y * scale, fres);

        const int ix0 = (int)xg;        // xg in [0, fres) -> trunc == floor
        const int iy0 = (int)yg;
        const float fx = xg - (float)ix0;
        const float fy = yg - (float)iy0;
        int ix1 = ix0 + 1; if (ix1 == res) ix1 = 0;

        const float w00 = (1.0f - fx) * (1.0f - fy);
        const float w10 = fx * (1.0f - fy);
        const float w01 = (1.0f - fx) * fy;
        const float w11 = fx * fy;

        if (v4ok) {
            // Branch-free uniform scatter (see R11): one v4 per row at the 16B
            // window containing iy0, plus predicated spill v4 for o==3.
            const int o   = iy0 & 3;
            const int iyb = iy0 & ~3;

            const bool e0 = (o == 0), e1 = (o == 1), e2 = (o == 2), e3 = (o == 3);

            const float a0 = e0 ? w00 : 0.0f;
            const float a1 = e1 ? w00 : (e0 ? w01 : 0.0f);
            const float a2 = e2 ? w00 : (e1 ? w01 : 0.0f);
            const float a3 = e3 ? w00 : (e2 ? w01 : 0.0f);

            const float b0 = e0 ? w10 : 0.0f;
            const float b1 = e1 ? w10 : (e0 ? w11 : 0.0f);
            const float b2 = e2 ? w10 : (e1 ? w11 : 0.0f);
            const float b3 = e3 ? w10 : (e2 ? w11 : 0.0f);

            red_add_v4(&out[ix0 * res + iyb], a0, a1, a2, a3);
            red_add_v4(&out[ix1 * res + iyb], b0, b1, b2, b3);

            if (e3) {
                int iy1 = iy0 + 1; if (iy1 == res) iy1 = 0;   // iy1 % 4 == 0
                red_add_v4(&out[ix0 * res + iy1], w01, 0.0f, 0.0f, 0.0f);
                red_add_v4(&out[ix1 * res + iy1], w11, 0.0f, 0.0f, 0.0f);
            }
        } else {
            int iy1 = iy0 + 1; if (iy1 == res) iy1 = 0;
            atomicAdd(&out[ix0 * res + iy0], w00);
            atomicAdd(&out[ix1 * res + iy0], w10);
            atomicAdd(&out[ix0 * res + iy1], w01);
            atomicAdd(&out[ix1 * res + iy1], w11);
        }
    }
}

extern "C" void kernel_launch(void* const* d_in, const int* in_sizes, int n_in,
                              void* d_out, int out_size) {
    const float* positions  = (const float*)d_in[0];
    const float* velocities = (const float*)d_in[1];
    const float* rotations  = (const float*)d_in[2];
    const float* observer   = (const float*)d_in[3];
    const float* r_centers  = (const float*)d_in[4];
    const float* widths     = (const float*)d_in[5];
    const float* t_p        = (const float*)d_in[6];
    const float* maxd_p     = (const float*)d_in[7];
    const float* box_p      = (const float*)d_in[8];
    const int*   shell_p    = (const int*)d_in[9];
    const int*   rotidx_p   = (const int*)d_in[10];
    const int*   res_p      = (const int*)d_in[11];
    float* out = (float*)d_out;

    const int n = in_sizes[0] / 3;

    cudaMemsetAsync(out, 0, (size_t)out_size * sizeof(float));

    const int threads = 256;
    const int nthreads_needed = (n + 1) / 2;
    const int blocks = (nthreads_needed + threads - 1) / threads;
    telephoto_paint_kernel<<<blocks, threads>>>(
        (const float2*)positions, (const float2*)velocities,
        rotations, observer, r_centers, widths,
        t_p, maxd_p, box_p, shell_p, rotidx_p, res_p, out, n);
}

// round 14
// speedup vs baseline: 1.1936x; 1.0125x over previous
#include <cuda_runtime.h>
#include <cuda_bf16.h>

// TelephotoInterp R14: R13 (best 75.1us) with ONE change — __ldcs (streaming,
// evict-first) on the six particle loads so the 201MB single-use input stream
// does not evict the 16.8MB grid from L2; all red ops should then hit L2.

__device__ __forceinline__ float fsqrt_ap(float x) {
    float r; asm("sqrt.approx.f32 %0, %1;" : "=f"(r) : "f"(x)); return r;
}
__device__ __forceinline__ float frcp_ap(float x) {
    float r; asm("rcp.approx.f32 %0, %1;" : "=f"(r) : "f"(x)); return r;
}
__device__ __forceinline__ float frsqrt_ap(float x) {
    float r; asm("rsqrt.approx.f32 %0, %1;" : "=f"(r) : "f"(x)); return r;
}
__device__ __forceinline__ void red_add_v4(float* addr, float a, float b, float c, float d) {
    asm volatile("red.global.add.v4.f32 [%0], {%1, %2, %3, %4};"
                 :: "l"(addr), "f"(a), "f"(b), "f"(c), "f"(d) : "memory");
}

__device__ __forceinline__ float wrapf(float g, float fres) {
    g = (g <  0.0f) ? g + fres : g;
    g = (g <  0.0f) ? g + fres : g;
    g = (g >= fres) ? g - fres : g;
    g = (g >= fres) ? g - fres : g;
    return g;
}

__global__ void telephoto_paint_kernel(
    const float2* __restrict__ pos2,
    const float2* __restrict__ vel2,
    const float* __restrict__ rotations,
    const float* __restrict__ observer,
    const float* __restrict__ r_centers,
    const float* __restrict__ widths,
    const float* __restrict__ t_p,
    const float* __restrict__ maxd_p,
    const float* __restrict__ box_p,
    const int*   __restrict__ shell_p,
    const int*   __restrict__ rotidx_p,
    const int*   __restrict__ res_p,
    float* __restrict__ out,
    int n)   // n = number of particles
{
    const int t = blockIdx.x * blockDim.x + threadIdx.x;
    const int base = 2 * t;
    if (base >= n) return;

    // Scalar params (uniform broadcast loads)
    const int   shell = shell_p[0];
    const float rc    = r_centers[shell];
    const float w     = widths[shell];
    const float maxd  = maxd_p[0];
    const float box   = box_p[0];
    const int   res   = res_p[0];
    const float fres  = (float)res;
    const bool inside = (rc + 0.5f * w <= maxd);
    const bool v4ok   = ((res & 3) == 0);
    const float ox = observer[0], oy = observer[1], oz = observer[2];
    const float zlo = rc - 0.5f * w;
    const float zhi = rc + 0.5f * w;
    const float scale = (float)res / box;

    // Rotation / drift params (only meaningful for telephoto branch)
    float m00=1.f,m01=0.f,m02=0.f,m10=0.f,m11=1.f,m12=0.f,m20=0.f,m21=0.f,m22=1.f;
    float tt = 0.f, shift = 0.f, gp_t = 0.f;
    if (!inside) {
        const int ridx = rotidx_p[0] % 47;
        const float* __restrict__ M = rotations + 9 * ridx;
        m00=M[0]; m01=M[1]; m02=M[2];
        m10=M[3]; m11=M[4]; m12=M[5];
        m20=M[6]; m21=M[7]; m22=M[8];
        tt = t_p[0];
        shift = floorf(rc / maxd) * maxd;
        gp_t = tt * sqrtf(tt);   // uniform scalar, IEEE is fine
    }

    // 2 particles = 6 floats = 3 float2 per array (always 8B-aligned).
    // Streaming loads: input is single-use; keep the grid resident in L2.
    float px[2], py[2], pz[2], vx[2], vy[2], vz[2];
    int cnt = 2;
    if (base + 1 < n) {
        const float2 pA = __ldcs(&pos2[3*t + 0]);   // x0 y0
        const float2 pB = __ldcs(&pos2[3*t + 1]);   // z0 x1
        const float2 pC = __ldcs(&pos2[3*t + 2]);   // y1 z1
        px[0]=pA.x; py[0]=pA.y; pz[0]=pB.x;
        px[1]=pB.y; py[1]=pC.x; pz[1]=pC.y;
        if (!inside) {
            const float2 vA = __ldcs(&vel2[3*t + 0]);
            const float2 vB = __ldcs(&vel2[3*t + 1]);
            const float2 vC = __ldcs(&vel2[3*t + 2]);
            vx[0]=vA.x; vy[0]=vA.y; vz[0]=vB.x;
            vx[1]=vB.y; vy[1]=vC.x; vz[1]=vC.y;
        }
    } else {
        cnt = 1;
        const float* pp = (const float*)pos2;
        const float* vv = (const float*)vel2;
        px[0] = pp[3*base+0]; py[0] = pp[3*base+1]; pz[0] = pp[3*base+2];
        if (!inside) {
            vx[0] = vv[3*base+0]; vy[0] = vv[3*base+1]; vz[0] = vv[3*base+2];
        }
    }

    #pragma unroll
    for (int k = 0; k < 2; k++) {
        if (k >= cnt) break;

        float X, Y;
        if (inside) {
            const float Z = pz[k];
            if (!(Z >= zlo && Z < zhi)) continue;   // sel==0 adds +0.0 -> skip
            X = px[k]; Y = py[k];
        } else {
            const float qx = px[k] - ox, qy = py[k] - oy, qz = pz[k] - oz;
            const float rx = m00*qx + m01*qy + m02*qz;
            const float ry = m10*qx + m11*qy + m12*qz;
            const float rz = m20*qx + m21*qy + m22*qz + shift;

            const float dxd = rx - ox, dyd = ry - oy, dzd = rz - oz;
            const float d2   = fmaf(dxd, dxd, fmaf(dyd, dyd, dzd*dzd));
            const float dist = fsqrt_ap(d2);

            const float a_tgt = frcp_ap(fmaf(dist, (1.0f/3000.0f), 1.0f));
            const float gp_a  = a_tgt * fsqrt_ap(a_tgt);          // a^1.5
            const float inv_q = frsqrt_ap(fsqrt_ap(tt * a_tgt));  // (t*a)^-0.25
            const float drift = (gp_a - gp_t) * (2.0f/3.0f) * inv_q;

            const float wz = m20*vx[k] + m21*vy[k] + m22*vz[k];
            const float Z  = rz + drift * wz + oz;
            if (!(Z >= zlo && Z < zhi)) continue;   // sel==0 adds +0.0 -> skip

            // Only accepted particles pay for X/Y
            const float wx = m00*vx[k] + m01*vy[k] + m02*vz[k];
            const float wy = m10*vx[k] + m11*vy[k] + m12*vz[k];
            X = rx + drift * wx + ox;
            Y = ry + drift * wy + oy;
        }

        // Float-domain periodic wrap, then floor (no integer modulo needed)
        const float xg = wrapf(X * scale, fres);
        const float yg = wrapf(Y * scale, fres);

        const int ix0 = (int)xg;        // xg in [0, fres) -> trunc == floor
        const int iy0 = (int)yg;
        const float fx = xg - (float)ix0;
        const float fy = yg - (float)iy0;
        int ix1 = ix0 + 1; if (ix1 == res) ix1 = 0;

        const float w00 = (1.0f - fx) * (1.0f - fy);
        const float w10 = fx * (1.0f - fy);
        const float w01 = (1.0f - fx) * fy;
        const float w11 = fx * fy;

        if (v4ok) {
            // Branch-free uniform scatter (see R11): one v4 per row at the 16B
            // window containing iy0, plus predicated spill v4 for o==3.
            const int o   = iy0 & 3;
            const int iyb = iy0 & ~3;

            const bool e0 = (o == 0), e1 = (o == 1), e2 = (o == 2), e3 = (o == 3);

            const float a0 = e0 ? w00 : 0.0f;
            const float a1 = e1 ? w00 : (e0 ? w01 : 0.0f);
            const float a2 = e2 ? w00 : (e1 ? w01 : 0.0f);
            const float a3 = e3 ? w00 : (e2 ? w01 : 0.0f);

            const float b0 = e0 ? w10 : 0.0f;
            const float b1 = e1 ? w10 : (e0 ? w11 : 0.0f);
            const float b2 = e2 ? w10 : (e1 ? w11 : 0.0f);
            const float b3 = e3 ? w10 : (e2 ? w11 : 0.0f);

            red_add_v4(&out[ix0 * res + iyb], a0, a1, a2, a3);
            red_add_v4(&out[ix1 * res + iyb], b0, b1, b2, b3);

            if (e3) {
                int iy1 = iy0 + 1; if (iy1 == res) iy1 = 0;   // iy1 % 4 == 0
                red_add_v4(&out[ix0 * res + iy1], w01, 0.0f, 0.0f, 0.0f);
                red_add_v4(&out[ix1 * res + iy1], w11, 0.0f, 0.0f, 0.0f);
            }
        } else {
            int iy1 = iy0 + 1; if (iy1 == res) iy1 = 0;
            atomicAdd(&out[ix0 * res + iy0], w00);
            atomicAdd(&out[ix1 * res + iy0], w10);
            atomicAdd(&out[ix0 * res + iy1], w01);
            atomicAdd(&out[ix1 * res + iy1], w11);
        }
    }
}

extern "C" void kernel_launch(void* const* d_in, const int* in_sizes, int n_in,
                              void* d_out, int out_size) {
    const float* positions  = (const float*)d_in[0];
    const float* velocities = (const float*)d_in[1];
    const float* rotations  = (const float*)d_in[2];
    const float* observer   = (const float*)d_in[3];
    const float* r_centers  = (const float*)d_in[4];
    const float* widths     = (const float*)d_in[5];
    const float* t_p        = (const float*)d_in[6];
    const float* maxd_p     = (const float*)d_in[7];
    const float* box_p      = (const float*)d_in[8];
    const int*   shell_p    = (const int*)d_in[9];
    const int*   rotidx_p   = (const int*)d_in[10];
    const int*   res_p      = (const int*)d_in[11];
    float* out = (float*)d_out;

    const int n = in_sizes[0] / 3;

    cudaMemsetAsync(out, 0, (size_t)out_size * sizeof(float));

    const int threads = 256;
    const int nthreads_needed = (n + 1) / 2;
    const int blocks = (nthreads_needed + threads - 1) / threads;
    telephoto_paint_kernel<<<blocks, threads>>>(
        (const float2*)positions, (const float2*)velocities,
        rotations, observer, r_centers, widths,
        t_p, maxd_p, box_p, shell_p, rotidx_p, res_p, out, n);
}